// round 15
// baseline (speedup 1.0000x reference)
#include <cuda_runtime.h>
#include <cstdint>
#include <math.h>

// ============================================================================
// SpikeFP32Tanh — full reference-pipeline emulation.
//
// KEY INSIGHT (R15): jnp.exp2(x) lowers to EXP(x * fl32(ln2)). With
// L = 0x3F317218 = 1453635*2^-21, fl(k*L) != k*L exactly for
// k in {13,15,17,19,21,23} (odd k*1453635 in (2^24,2^25), ties-to-even
// rounds by +-2^-21). Hence the reference's encode tables man_pw[k] =
// EXP(fl(kL)) are off by ~4 ulps at those k, and its floor/mod bit
// extraction systematically flips low mantissa bits — an artifact floor of
// ~0.9 flipped bits/value (rel ~0.237) that NO ideal-math kernel can match.
// This explains eight exp variants plateauing at 0.26-0.28.
//
// This kernel emulates the pipeline: tables from REF_EXP, decode
// v = fl(exp2tab*(1+frac)), encode via m0/m with perturbed exp2, one-step
// exponent correction, per-bit floor(fl(m*ptab[k])) & 1.
//
// REF_EXP profile (remaining unknown): XLA:CPU GenerateVF32Exp transcription
// (fused fx, unfused two-constant reduction, fused Horner).
// ============================================================================

#define FULL_MASK 0xffffffffu
#define LN2F 0.693147182464599609375f   /* fl32(log(2)) = 0x3F317218 */

extern "C" __device__ float __nv_expf(float);

#ifndef EXP_PROFILE
#define EXP_PROFILE 0   /* 0=XLA:CPU mixed, 1=all-fused, 2=all-unfused, 3=libdevice */
#endif

__device__ __forceinline__ float ref_exp(float inp) {
#if EXP_PROFILE == 3
    return __nv_expf(inp);
#else
    float x = fminf(fmaxf(inp, -88.3762626647949f), 88.3762626647950f);
#if EXP_PROFILE == 2
    float fx = floorf(__fadd_rn(__fmul_rn(x, 1.44269504088896341f), 0.5f));
#else
    float fx = floorf(__fmaf_rn(x, 1.44269504088896341f, 0.5f));
#endif
#if EXP_PROFILE == 1
    float xx = __fmaf_rn(-0.693359375f, fx, x);
    xx = __fmaf_rn(2.12194440e-4f, fx, xx);
#else
    float tmp = __fmul_rn(0.693359375f, fx);
    float z0  = __fmul_rn(-2.12194440e-4f, fx);
    float xx = __fsub_rn(x, tmp);
    xx = __fsub_rn(xx, z0);
#endif
    float z = __fmul_rn(xx, xx);
    float y = __fmaf_rn(1.9875691500E-4f, xx, 1.3981999507E-3f);
    y = __fmaf_rn(y, xx, 8.3334519073E-3f);
    y = __fmaf_rn(y, xx, 4.1665795894E-2f);
    y = __fmaf_rn(y, xx, 1.6666665459E-1f);
    y = __fmaf_rn(y, xx, 5.0000001201E-1f);
    y = __fmaf_rn(y, z, xx);
    y = __fadd_rn(y, 1.0f);
    int n = (int)fx;
    float p2n = __uint_as_float((unsigned)(n + 127) << 23);
    return __fmul_rn(y, p2n);
#endif
}

__global__ __launch_bounds__(256)
void spike_fp32_tanh_kernel(const float* __restrict__ x,
                            float* __restrict__ out,
                            int nvals) {
    // ---- reference exp2 tables: ptab[k]=EXP2(+k), ntab[k]=EXP2(-k) ---------
    __shared__ float ptab[32];
    __shared__ float ntab[32];
    {
        int tid = threadIdx.x;
        if (tid < 32)
            ptab[tid] = ref_exp(__fmul_rn((float)tid, LN2F));
        else if (tid < 64)
            ntab[tid - 32] = ref_exp(__fmul_rn(-(float)(tid - 32), LN2F));
    }
    __syncthreads();

    const int lane = threadIdx.x & 31;
    const int warp_global = (int)((blockIdx.x * blockDim.x + threadIdx.x) >> 5);
    const long long vbase = (long long)warp_global * 32;
    if (vbase >= nvals) return;
    const int count = (nvals - vbase >= 32) ? 32 : (int)(nvals - vbase);

    const float* __restrict__ px = x + vbase * 32;
    float* __restrict__ po = out + vbase * 32;

    // ---- gather the 32 input bits (ballot-transpose) -----------------------
    unsigned rword = 0;
    #pragma unroll
    for (int v = 0; v < 32; ++v) {
        float f = (v < count) ? px[v * 32 + lane] : 0.0f;
        unsigned m = __ballot_sync(FULL_MASK, f != 0.0f);
        if (lane == v) rword = m;
    }
    const unsigned ieee = __brev(rword);
    const unsigned sbit = ieee >> 31;
    const int eint = (int)((ieee >> 23) & 0xFF);     // > 0 (normals only)
    const unsigned fm = ieee & 0x7FFFFFu;

    // ---- reference DECODE: v = sign * EXP2(e-127) * (1+frac) ---------------
    const float frac1 = __uint_as_float(0x3F800000u | fm);   // exact 1+frac
    int Edec = eint - 127;                                   // [-24, 2] here
    if (Edec > 31) Edec = 31; if (Edec < -31) Edec = -31;    // safety clamp
    const float p2E = (Edec >= 0) ? ptab[Edec] : ntab[-Edec];
    const float mag = __fmul_rn(p2E, frac1);
    const float v = sbit ? -mag : mag;

    // ---- tanh: t = (EXP(2v)-1)/(EXP(2v)+1), IEEE rn div --------------------
    const float e2x = ref_exp(__fmul_rn(2.0f, v));
    const float t = __fdiv_rn(__fsub_rn(e2x, 1.0f), __fadd_rn(e2x, 1.0f));

    // ---- reference ENCODE (with perturbed exp2 tables) ---------------------
    const unsigned so = (t < 0.0f) ? 1u : 0u;
    const float a = fmaxf(fabsf(t), 1.17549435e-38f);
    // floor(log2(a)) lands on the true exponent (correction absorbs log ulps)
    int E = (int)((__float_as_uint(a) >> 23) & 0xFF) - 127;  // <= -1 here
    int k0 = -E; if (k0 < 0) k0 = 0; if (k0 > 31) k0 = 31;
    const float m0 = __fmul_rn(a, ptab[k0]);                 // a * EXP2(-E)
    int ec = E + ((m0 >= 2.0f) ? 1 : 0) - ((m0 < 1.0f) ? 1 : 0);
    if (ec < -126) ec = -126; if (ec > 127) ec = 127;        // clip
    int kc = -ec; if (kc < 0) kc = 0; if (kc > 31) kc = 31;
    const float m = __fsub_rn(__fmul_rn(a, ptab[kc]), 1.0f); // a*EXP2(-e) - 1
    const unsigned biased = (unsigned)(ec + 127);
    // mantissa bits: mod(floor(fl(m * EXP2(k))), 2)  — artifact-faithful
    unsigned mant = 0;
    #pragma unroll
    for (int k = 1; k <= 23; ++k) {
        int fk = (int)floorf(__fmul_rn(m, ptab[k]));
        mant |= (unsigned)(fk & 1) << (23 - k);
    }
    const unsigned obits = (so << 31) | (biased << 23) | mant;
    const unsigned orev = __brev(obits);

    // ---- scatter the 32 output bits (shfl + coalesced stores) --------------
    #pragma unroll
    for (int vv = 0; vv < 32; ++vv) {
        unsigned rw = __shfl_sync(FULL_MASK, orev, vv);
        if (vv < count)
            po[vv * 32 + lane] = __uint_as_float(((rw >> lane) & 1u) * 0x3f800000u);
    }
}

extern "C" void kernel_launch(void* const* d_in, const int* in_sizes, int n_in,
                              void* d_out, int out_size) {
    const float* x = (const float*)d_in[0];
    float* out = (float*)d_out;
    const long long total = (long long)in_sizes[0];
    const int nvals = (int)(total / 32);          // 4096*1024 = 4,194,304
    const int threads = 256;
    const int warps_needed = (nvals + 31) / 32;
    const int wpb = threads / 32;
    const int blocks = (warps_needed + wpb - 1) / wpb;
    spike_fp32_tanh_kernel<<<blocks, threads>>>(x, out, nvals);
}

// round 16
// speedup vs baseline: 1.0031x; 1.0031x over previous
#include <cuda_runtime.h>
#include <cstdint>
#include <math.h>

// ============================================================================
// SpikeFP32Tanh — reference-pipeline emulation (PASSING R15: 164us, rel 3.8e-4)
//
// Reference quirk being emulated: jnp.exp2(x) lowers to EXP(x*fl32(ln2)), and
// fl(k*ln2) != k*ln2 for k in {13,15,17,19,21,23} -> the reference's encode
// tables are ~4ulp off at those k, flipping low mantissa bits. We reproduce
// the pipeline with REF_EXP = XLA:CPU GenerateVF32Exp (fused fx, unfused
// two-constant reduction, fused Horner).
//
// R16 optimization: encode loop 23 float floor-muls -> 1 exact fixed-point
// extraction (floor(m*2^53), valid because ptab[k]==2^k exactly for the 17
// unperturbed k — runtime-verified, block-uniform fallback otherwise) + 6
// artifact-faithful perturbed bits. Streaming cache hints on the 1GB stream.
// ============================================================================

#define FULL_MASK 0xffffffffu
#define LN2F 0.693147182464599609375f   /* fl32(log(2)) = 0x3F317218 */

__device__ __forceinline__ float ref_exp(float inp) {
    float x = fminf(fmaxf(inp, -88.3762626647949f), 88.3762626647950f);
    float fx = floorf(__fmaf_rn(x, 1.44269504088896341f, 0.5f));
    float tmp = __fmul_rn(0.693359375f, fx);
    float z0  = __fmul_rn(-2.12194440e-4f, fx);
    float xx = __fsub_rn(x, tmp);
    xx = __fsub_rn(xx, z0);
    float z = __fmul_rn(xx, xx);
    float y = __fmaf_rn(1.9875691500E-4f, xx, 1.3981999507E-3f);
    y = __fmaf_rn(y, xx, 8.3334519073E-3f);
    y = __fmaf_rn(y, xx, 4.1665795894E-2f);
    y = __fmaf_rn(y, xx, 1.6666665459E-1f);
    y = __fmaf_rn(y, xx, 5.0000001201E-1f);
    y = __fmaf_rn(y, z, xx);
    y = __fadd_rn(y, 1.0f);
    int n = (int)fx;
    float p2n = __uint_as_float((unsigned)(n + 127) << 23);
    return __fmul_rn(y, p2n);
}

__global__ __launch_bounds__(256)
void spike_fp32_tanh_kernel(const float* __restrict__ x,
                            float* __restrict__ out,
                            int nvals) {
    // ---- reference exp2 tables: ptab[k]=EXP2(+k), ntab[k]=EXP2(-k) ---------
    __shared__ float ptab[32];
    __shared__ float ntab[32];
    __shared__ int   s_fast;   // 1 if ptab[k]==2^k exactly for unperturbed k
    {
        int tid = threadIdx.x;
        if (tid < 32)
            ptab[tid] = ref_exp(__fmul_rn((float)tid, LN2F));
        else if (tid < 64)
            ntab[tid - 32] = ref_exp(__fmul_rn(-(float)(tid - 32), LN2F));
        if (tid == 64) s_fast = 1;
    }
    __syncthreads();
    if (threadIdx.x == 0) {
        // verify the fast-path premise for the 17 unperturbed k in [1,23]
        int ok = 1;
        #pragma unroll
        for (int k = 1; k <= 23; ++k) {
            bool pert = (k >= 13) && (k & 1);          // {13,15,17,19,21,23}
            if (!pert) {
                float exact = __uint_as_float((unsigned)(k + 127) << 23);
                if (ptab[k] != exact) ok = 0;
            }
        }
        if (!ok) s_fast = 0;
    }
    __syncthreads();
    const bool fastmant = (s_fast != 0);

    const int lane = threadIdx.x & 31;
    const int warp_global = (int)((blockIdx.x * blockDim.x + threadIdx.x) >> 5);
    const long long vbase = (long long)warp_global * 32;
    if (vbase >= nvals) return;
    const int count = (nvals - vbase >= 32) ? 32 : (int)(nvals - vbase);

    const float* __restrict__ px = x + vbase * 32;
    float* __restrict__ po = out + vbase * 32;

    // ---- gather the 32 input bits (ballot-transpose, streaming loads) ------
    unsigned rword = 0;
    #pragma unroll
    for (int v = 0; v < 32; ++v) {
        float f = (v < count) ? __ldcs(px + v * 32 + lane) : 0.0f;
        unsigned m = __ballot_sync(FULL_MASK, f != 0.0f);
        if (lane == v) rword = m;
    }
    const unsigned ieee = __brev(rword);
    const unsigned sbit = ieee >> 31;
    const int eint = (int)((ieee >> 23) & 0xFF);     // > 0 (normals only)
    const unsigned fm = ieee & 0x7FFFFFu;

    // ---- reference DECODE: v = sign * EXP2(e-127) * (1+frac) ---------------
    const float frac1 = __uint_as_float(0x3F800000u | fm);   // exact 1+frac
    int Edec = eint - 127;
    if (Edec > 31) Edec = 31; if (Edec < -31) Edec = -31;    // safety clamp
    const float p2E = (Edec >= 0) ? ptab[Edec] : ntab[-Edec];
    const float mag = __fmul_rn(p2E, frac1);
    const float v = sbit ? -mag : mag;

    // ---- tanh: t = (EXP(2v)-1)/(EXP(2v)+1), IEEE rn div --------------------
    const float e2x = ref_exp(__fmul_rn(2.0f, v));
    const float t = __fdiv_rn(__fsub_rn(e2x, 1.0f), __fadd_rn(e2x, 1.0f));

    // ---- reference ENCODE (with perturbed exp2 tables) ---------------------
    const unsigned so = (t < 0.0f) ? 1u : 0u;
    const float a = fmaxf(fabsf(t), 1.17549435e-38f);
    int E = (int)((__float_as_uint(a) >> 23) & 0xFF) - 127;  // true floor(log2)
    int k0 = -E; if (k0 < 0) k0 = 0; if (k0 > 31) k0 = 31;
    const float m0 = __fmul_rn(a, ptab[k0]);                 // a * EXP2(-E)
    int ec = E + ((m0 >= 2.0f) ? 1 : 0) - ((m0 < 1.0f) ? 1 : 0);
    if (ec < -126) ec = -126; if (ec > 127) ec = 127;
    int kc = -ec; if (kc < 0) kc = 0; if (kc > 31) kc = 31;
    const float m = __fsub_rn(__fmul_rn(a, ptab[kc]), 1.0f); // a*EXP2(-e) - 1
    const unsigned biased = (unsigned)(ec + 127);

    unsigned mant;
    if (fastmant) {
        // Exact fixed-point bits for the 17 unperturbed k: scaling by 2^53 is
        // exact; floor(m*2^k) = (floor(m*2^53) >> (53-k)) (arithmetic shift,
        // handles tiny-negative m identically to jnp.mod(floor(..),2)).
        long long fix = __float2ll_rd(__fmul_rn(m, 9007199254740992.0f));
        unsigned mant_exact = (unsigned)(fix >> 30) & 0x7FFFFFu;
        // 6 perturbed bits (artifact-faithful float path), positions {10,8,6,4,2,0}
        unsigned pb = 0;
        #pragma unroll
        for (int k = 13; k <= 23; k += 2) {
            int fk = __float2int_rd(__fmul_rn(m, ptab[k]));
            pb |= (unsigned)(fk & 1) << (23 - k);
        }
        mant = (mant_exact & ~0x555u) | pb;
    } else {
        mant = 0;
        #pragma unroll
        for (int k = 1; k <= 23; ++k) {
            int fk = __float2int_rd(__fmul_rn(m, ptab[k]));
            mant |= (unsigned)(fk & 1) << (23 - k);
        }
    }
    const unsigned obits = (so << 31) | (biased << 23) | mant;
    const unsigned orev = __brev(obits);

    // ---- scatter the 32 output bits (shfl + streaming stores) --------------
    #pragma unroll
    for (int vv = 0; vv < 32; ++vv) {
        unsigned rw = __shfl_sync(FULL_MASK, orev, vv);
        if (vv < count)
            __stcs(po + vv * 32 + lane,
                   __uint_as_float(((rw >> lane) & 1u) * 0x3f800000u));
    }
}

extern "C" void kernel_launch(void* const* d_in, const int* in_sizes, int n_in,
                              void* d_out, int out_size) {
    const float* x = (const float*)d_in[0];
    float* out = (float*)d_out;
    const long long total = (long long)in_sizes[0];
    const int nvals = (int)(total / 32);          // 4096*1024 = 4,194,304
    const int threads = 256;
    const int warps_needed = (nvals + 31) / 32;
    const int wpb = threads / 32;
    const int blocks = (warps_needed + wpb - 1) / wpb;
    spike_fp32_tanh_kernel<<<blocks, threads>>>(x, out, nvals);
}

// round 17
// speedup vs baseline: 1.0033x; 1.0002x over previous
#include <cuda_runtime.h>
#include <cstdint>
#include <math.h>

// ============================================================================
// SpikeFP32Tanh — reference-pipeline emulation (PASSING: 163.9us, rel 3.8e-4)
//
// Emulates the reference's jnp.exp2 quirk: exp2(x) = EXP(x*fl32(ln2)), with
// fl(k*ln2) != k*ln2 for k in {13,15,17,19,21,23} -> perturbed encode tables.
// REF_EXP = XLA:CPU GenerateVF32Exp (fused fx, unfused reduction, fused Horner).
//
// R17: transpose-loop slimming (the real ALU hog per R16 post-mortem):
//  - count==32 always (nvals % 32 == 0): unconditional fast-path loops
//  - scatter via float4 / STG.128: 8 shfl + 8 stores instead of 32 + 32
// ============================================================================

#define FULL_MASK 0xffffffffu
#define LN2F 0.693147182464599609375f   /* fl32(log(2)) = 0x3F317218 */

__device__ __forceinline__ float ref_exp(float inp) {
    float x = fminf(fmaxf(inp, -88.3762626647949f), 88.3762626647950f);
    float fx = floorf(__fmaf_rn(x, 1.44269504088896341f, 0.5f));
    float tmp = __fmul_rn(0.693359375f, fx);
    float z0  = __fmul_rn(-2.12194440e-4f, fx);
    float xx = __fsub_rn(x, tmp);
    xx = __fsub_rn(xx, z0);
    float z = __fmul_rn(xx, xx);
    float y = __fmaf_rn(1.9875691500E-4f, xx, 1.3981999507E-3f);
    y = __fmaf_rn(y, xx, 8.3334519073E-3f);
    y = __fmaf_rn(y, xx, 4.1665795894E-2f);
    y = __fmaf_rn(y, xx, 1.6666665459E-1f);
    y = __fmaf_rn(y, xx, 5.0000001201E-1f);
    y = __fmaf_rn(y, z, xx);
    y = __fadd_rn(y, 1.0f);
    int n = (int)fx;
    float p2n = __uint_as_float((unsigned)(n + 127) << 23);
    return __fmul_rn(y, p2n);
}

__global__ __launch_bounds__(256)
void spike_fp32_tanh_kernel(const float* __restrict__ x,
                            float* __restrict__ out,
                            int nvals) {
    // ---- reference exp2 tables: ptab[k]=EXP2(+k), ntab[k]=EXP2(-k) ---------
    __shared__ float ptab[32];
    __shared__ float ntab[32];
    __shared__ int   s_fast;
    {
        int tid = threadIdx.x;
        if (tid < 32)
            ptab[tid] = ref_exp(__fmul_rn((float)tid, LN2F));
        else if (tid < 64)
            ntab[tid - 32] = ref_exp(__fmul_rn(-(float)(tid - 32), LN2F));
        if (tid == 64) s_fast = 1;
    }
    __syncthreads();
    if (threadIdx.x == 0) {
        int ok = 1;
        #pragma unroll
        for (int k = 1; k <= 23; ++k) {
            bool pert = (k >= 13) && (k & 1);          // {13,15,17,19,21,23}
            if (!pert) {
                float exact = __uint_as_float((unsigned)(k + 127) << 23);
                if (ptab[k] != exact) ok = 0;
            }
        }
        if (!ok) s_fast = 0;
    }
    __syncthreads();
    const bool fastmant = (s_fast != 0);

    const int lane = threadIdx.x & 31;
    const int warp_global = (int)((blockIdx.x * blockDim.x + threadIdx.x) >> 5);
    const long long vbase = (long long)warp_global * 32;
    if (vbase >= nvals) return;
    const bool full = (nvals - vbase) >= 32;

    const float* __restrict__ px = x + vbase * 32;
    float* __restrict__ po = out + vbase * 32;

    // ---- gather the 32 input bits (ballot-transpose) -----------------------
    unsigned rword = 0;
    if (full) {
        #pragma unroll
        for (int v = 0; v < 32; ++v) {
            float f = __ldcs(px + v * 32 + lane);
            unsigned m = __ballot_sync(FULL_MASK, f != 0.0f);
            if (lane == v) rword = m;
        }
    } else {
        const int count = (int)(nvals - vbase);
        #pragma unroll
        for (int v = 0; v < 32; ++v) {
            float f = (v < count) ? __ldcs(px + v * 32 + lane) : 0.0f;
            unsigned m = __ballot_sync(FULL_MASK, f != 0.0f);
            if (lane == v) rword = m;
        }
    }
    const unsigned ieee = __brev(rword);
    const unsigned sbit = ieee >> 31;
    const int eint = (int)((ieee >> 23) & 0xFF);     // > 0 (normals only)
    const unsigned fm = ieee & 0x7FFFFFu;

    // ---- reference DECODE: v = sign * EXP2(e-127) * (1+frac) ---------------
    const float frac1 = __uint_as_float(0x3F800000u | fm);
    int Edec = eint - 127;
    if (Edec > 31) Edec = 31; if (Edec < -31) Edec = -31;
    const float p2E = (Edec >= 0) ? ptab[Edec] : ntab[-Edec];
    const float mag = __fmul_rn(p2E, frac1);
    const float v = sbit ? -mag : mag;

    // ---- tanh: t = (EXP(2v)-1)/(EXP(2v)+1), IEEE rn div --------------------
    const float e2x = ref_exp(__fmul_rn(2.0f, v));
    const float t = __fdiv_rn(__fsub_rn(e2x, 1.0f), __fadd_rn(e2x, 1.0f));

    // ---- reference ENCODE (with perturbed exp2 tables) ---------------------
    const unsigned so = (t < 0.0f) ? 1u : 0u;
    const float a = fmaxf(fabsf(t), 1.17549435e-38f);
    int E = (int)((__float_as_uint(a) >> 23) & 0xFF) - 127;
    int k0 = -E; if (k0 < 0) k0 = 0; if (k0 > 31) k0 = 31;
    const float m0 = __fmul_rn(a, ptab[k0]);
    int ec = E + ((m0 >= 2.0f) ? 1 : 0) - ((m0 < 1.0f) ? 1 : 0);
    if (ec < -126) ec = -126; if (ec > 127) ec = 127;
    int kc = -ec; if (kc < 0) kc = 0; if (kc > 31) kc = 31;
    const float m = __fsub_rn(__fmul_rn(a, ptab[kc]), 1.0f);
    const unsigned biased = (unsigned)(ec + 127);

    unsigned mant;
    if (fastmant) {
        long long fix = __float2ll_rd(__fmul_rn(m, 9007199254740992.0f));
        unsigned mant_exact = (unsigned)(fix >> 30) & 0x7FFFFFu;
        unsigned pb = 0;
        #pragma unroll
        for (int k = 13; k <= 23; k += 2) {
            int fk = __float2int_rd(__fmul_rn(m, ptab[k]));
            pb |= (unsigned)(fk & 1) << (23 - k);
        }
        mant = (mant_exact & ~0x555u) | pb;
    } else {
        mant = 0;
        #pragma unroll
        for (int k = 1; k <= 23; ++k) {
            int fk = __float2int_rd(__fmul_rn(m, ptab[k]));
            mant |= (unsigned)(fk & 1) << (23 - k);
        }
    }
    const unsigned obits = (so << 31) | (biased << 23) | mant;
    const unsigned orev = __brev(obits);

    // ---- scatter: float4 planes, 8 shfl + 8 STG.128 ------------------------
    if (full) {
        float4* __restrict__ po4 = reinterpret_cast<float4*>(po);
        const int sub = lane >> 3;          // which plane within the group
        const int b   = (lane & 7) * 4;     // bit base within the plane
        #pragma unroll
        for (int g = 0; g < 8; ++g) {
            unsigned rw = __shfl_sync(FULL_MASK, orev, g * 4 + sub);
            float4 o;
            o.x = __uint_as_float(((rw >> (b + 0)) & 1u) * 0x3f800000u);
            o.y = __uint_as_float(((rw >> (b + 1)) & 1u) * 0x3f800000u);
            o.z = __uint_as_float(((rw >> (b + 2)) & 1u) * 0x3f800000u);
            o.w = __uint_as_float(((rw >> (b + 3)) & 1u) * 0x3f800000u);
            __stcs(po4 + g * 32 + lane, o);
        }
    } else {
        const int count = (int)(nvals - vbase);
        #pragma unroll
        for (int vv = 0; vv < 32; ++vv) {
            unsigned rw = __shfl_sync(FULL_MASK, orev, vv);
            if (vv < count)
                po[vv * 32 + lane] =
                    __uint_as_float(((rw >> lane) & 1u) * 0x3f800000u);
        }
    }
}

extern "C" void kernel_launch(void* const* d_in, const int* in_sizes, int n_in,
                              void* d_out, int out_size) {
    const float* x = (const float*)d_in[0];
    float* out = (float*)d_out;
    const long long total = (long long)in_sizes[0];
    const int nvals = (int)(total / 32);          // 4096*1024 = 4,194,304
    const int threads = 256;
    const int warps_needed = (nvals + 31) / 32;
    const int wpb = threads / 32;
    const int blocks = (warps_needed + wpb - 1) / wpb;
    spike_fp32_tanh_kernel<<<blocks, threads>>>(x, out, nvals);
}